// round 2
// baseline (speedup 1.0000x reference)
#include <cuda_runtime.h>
#include <math.h>

// ---------------------------------------------------------------------------
// GeneratorRNN: MLP(512->32->64) -> gates(64->128) -> LSTM(H=32) -> MLP(32->64->512)
// B=128, S=1024, F=512, T = 131072 tokens.
// ---------------------------------------------------------------------------

#define T_TOKENS (128 * 1024)
#define TT 128  // tokens per block in GEMM phases

// Scratch (allocation-free rule: __device__ globals)
__device__ float g_xg[(size_t)T_TOKENS * 128];  // 64 MB: input-side gate preacts
__device__ float g_hs[(size_t)T_TOKENS * 32];   // 16 MB: LSTM hidden outputs

__device__ __forceinline__ float fast_tanh(float x) {
    x = fminf(fmaxf(x, -15.f), 15.f);
    float e = __expf(2.f * x);
    return __fdividef(e - 1.f, e + 1.f);
}
__device__ __forceinline__ float fast_sig(float x) {
    x = fminf(fmaxf(x, -30.f), 30.f);
    return __fdividef(1.f, 1.f + __expf(-x));
}

// ---------------------------------------------------------------------------
// Phase 1: xg[t][128] = tanh(tanh(x@W1+b1)@W2+b2)@Wx + bl
// Block: 256 threads, 128 tokens. Shared-tiled fp32 GEMMs.
// ---------------------------------------------------------------------------
__global__ void __launch_bounds__(256, 1)
phase1_kernel(const float* __restrict__ x,
              const float* __restrict__ W1, const float* __restrict__ b1,
              const float* __restrict__ W2, const float* __restrict__ b2,
              const float* __restrict__ Wx, const float* __restrict__ bl)
{
    extern __shared__ float sm[];
    float* xs  = sm;               // [128][36]  x k-chunk (token-major, pad 4)
    float* w1s = xs  + TT * 36;    // [32][32]
    float* h1s = w1s + 32 * 32;    // [128][36]
    float* w2s = h1s + TT * 36;    // [32][64]
    float* h2s = w2s + 32 * 64;    // [128][68]
    float* wxs = h2s + TT * 68;    // [64][128]

    const int tid = threadIdx.x;
    const int tx = tid & 7;        // output group
    const int ty = tid >> 3;       // token group (x4)
    const int t0 = blockIdx.x * TT;

    for (int i = tid; i < 32 * 64; i += 256) w2s[i] = W2[i];
    for (int i = tid; i < 64 * 128; i += 256) wxs[i] = Wx[i];

    // ---- GEMM1: [128 tok][32 out], K=512 in chunks of 32 ----
    float acc[4][4];
#pragma unroll
    for (int i = 0; i < 4; i++)
#pragma unroll
        for (int j = 0; j < 4; j++) acc[i][j] = 0.f;

    for (int k0 = 0; k0 < 512; k0 += 32) {
        __syncthreads();
#pragma unroll
        for (int i = 0; i < 4; i++) {
            int slot = tid + i * 256;
            int tok = slot >> 3, kc = slot & 7;
            float4 v = *(const float4*)(x + (size_t)(t0 + tok) * 512 + k0 + kc * 4);
            *(float4*)(xs + tok * 36 + kc * 4) = v;
        }
        {
            int k = tid >> 3, j4 = tid & 7;
            *(float4*)(w1s + k * 32 + j4 * 4) =
                *(const float4*)(W1 + (size_t)(k0 + k) * 32 + j4 * 4);
        }
        __syncthreads();
#pragma unroll
        for (int k = 0; k < 32; k++) {
            float4 bv = *(const float4*)(w1s + k * 32 + tx * 4);
#pragma unroll
            for (int i = 0; i < 4; i++) {
                float a = xs[(ty * 4 + i) * 36 + k];
                acc[i][0] = fmaf(a, bv.x, acc[i][0]);
                acc[i][1] = fmaf(a, bv.y, acc[i][1]);
                acc[i][2] = fmaf(a, bv.z, acc[i][2]);
                acc[i][3] = fmaf(a, bv.w, acc[i][3]);
            }
        }
    }
    {
        float4 bb = *(const float4*)(b1 + tx * 4);
#pragma unroll
        for (int i = 0; i < 4; i++) {
            float4 hv;
            hv.x = fast_tanh(acc[i][0] + bb.x);
            hv.y = fast_tanh(acc[i][1] + bb.y);
            hv.z = fast_tanh(acc[i][2] + bb.z);
            hv.w = fast_tanh(acc[i][3] + bb.w);
            *(float4*)(h1s + (ty * 4 + i) * 36 + tx * 4) = hv;
        }
    }
    __syncthreads();

    // ---- GEMM2: [128][64], K=32. outs = {4tx+32j : j=0,1} ----
    float acc2[4][8];
#pragma unroll
    for (int i = 0; i < 4; i++)
#pragma unroll
        for (int j = 0; j < 8; j++) acc2[i][j] = 0.f;

#pragma unroll
    for (int k = 0; k < 32; k++) {
        float4 b0 = *(const float4*)(w2s + k * 64 + tx * 4);
        float4 b1v = *(const float4*)(w2s + k * 64 + tx * 4 + 32);
#pragma unroll
        for (int i = 0; i < 4; i++) {
            float a = h1s[(ty * 4 + i) * 36 + k];
            acc2[i][0] = fmaf(a, b0.x, acc2[i][0]);
            acc2[i][1] = fmaf(a, b0.y, acc2[i][1]);
            acc2[i][2] = fmaf(a, b0.z, acc2[i][2]);
            acc2[i][3] = fmaf(a, b0.w, acc2[i][3]);
            acc2[i][4] = fmaf(a, b1v.x, acc2[i][4]);
            acc2[i][5] = fmaf(a, b1v.y, acc2[i][5]);
            acc2[i][6] = fmaf(a, b1v.z, acc2[i][6]);
            acc2[i][7] = fmaf(a, b1v.w, acc2[i][7]);
        }
    }
#pragma unroll
    for (int j2 = 0; j2 < 2; j2++) {
        float4 bb = *(const float4*)(b2 + tx * 4 + 32 * j2);
#pragma unroll
        for (int i = 0; i < 4; i++) {
            float4 hv;
            hv.x = fast_tanh(acc2[i][4 * j2 + 0] + bb.x);
            hv.y = fast_tanh(acc2[i][4 * j2 + 1] + bb.y);
            hv.z = fast_tanh(acc2[i][4 * j2 + 2] + bb.z);
            hv.w = fast_tanh(acc2[i][4 * j2 + 3] + bb.w);
            *(float4*)(h2s + (ty * 4 + i) * 68 + tx * 4 + 32 * j2) = hv;
        }
    }
    __syncthreads();

    // ---- GEMM3: [128][128], K=64. outs = {4tx+32j : j=0..3} ----
    float acc3[4][16];
#pragma unroll
    for (int i = 0; i < 4; i++)
#pragma unroll
        for (int j = 0; j < 16; j++) acc3[i][j] = 0.f;

#pragma unroll
    for (int k = 0; k < 64; k++) {
        float4 bv[4];
#pragma unroll
        for (int j = 0; j < 4; j++)
            bv[j] = *(const float4*)(wxs + k * 128 + tx * 4 + 32 * j);
#pragma unroll
        for (int i = 0; i < 4; i++) {
            float a = h2s[(ty * 4 + i) * 68 + k];
#pragma unroll
            for (int j = 0; j < 4; j++) {
                acc3[i][4 * j + 0] = fmaf(a, bv[j].x, acc3[i][4 * j + 0]);
                acc3[i][4 * j + 1] = fmaf(a, bv[j].y, acc3[i][4 * j + 1]);
                acc3[i][4 * j + 2] = fmaf(a, bv[j].z, acc3[i][4 * j + 2]);
                acc3[i][4 * j + 3] = fmaf(a, bv[j].w, acc3[i][4 * j + 3]);
            }
        }
    }
#pragma unroll
    for (int j = 0; j < 4; j++) {
        float4 bb = *(const float4*)(bl + tx * 4 + 32 * j);
#pragma unroll
        for (int i = 0; i < 4; i++) {
            float4 ov;
            ov.x = acc3[i][4 * j + 0] + bb.x;
            ov.y = acc3[i][4 * j + 1] + bb.y;
            ov.z = acc3[i][4 * j + 2] + bb.z;
            ov.w = acc3[i][4 * j + 3] + bb.w;
            *(float4*)(g_xg + (size_t)(t0 + ty * 4 + i) * 128 + tx * 4 + 32 * j) = ov;
        }
    }
}

// ---------------------------------------------------------------------------
// Phase 2: LSTM scan. One warp per batch row. Lane n owns gate columns
// {n, n+32, n+64, n+96} of Wh in registers; h broadcast via shfl.
// Each gate reduction split into two 16-deep FMA chains to shorten the
// serial RAW chain (128 -> ~70 cycles) at the step boundary.
// ---------------------------------------------------------------------------
__global__ void __launch_bounds__(32)
lstm_kernel(const float* __restrict__ Wh)
{
    const int b = blockIdx.x;
    const int lane = threadIdx.x;

    float whi[32], whf[32], whg[32], who[32];
#pragma unroll
    for (int k = 0; k < 32; k++) {
        const float* r = Wh + k * 128;
        whi[k] = r[lane];
        whf[k] = r[32 + lane];
        whg[k] = r[64 + lane];
        who[k] = r[96 + lane];
    }

    const float* xb = g_xg + (size_t)b * 1024 * 128;
    float* hb = g_hs + (size_t)b * 1024 * 32;

    float c = 0.f, h = 0.f;
    float pi = xb[lane], pf = xb[32 + lane], pg = xb[64 + lane], po = xb[96 + lane];

    for (int t = 0; t < 1024; t++) {
        float gi0 = pi, gf0 = pf, gg0 = pg, go0 = po;
        float gi1 = 0.f, gf1 = 0.f, gg1 = 0.f, go1 = 0.f;
        if (t < 1023) {  // prefetch next step's gate preacts
            const float* n = xb + (size_t)(t + 1) * 128;
            pi = n[lane]; pf = n[32 + lane]; pg = n[64 + lane]; po = n[96 + lane];
        }
#pragma unroll
        for (int k = 0; k < 16; k++) {
            float hk0 = __shfl_sync(0xffffffffu, h, k);
            float hk1 = __shfl_sync(0xffffffffu, h, k + 16);
            gi0 = fmaf(hk0, whi[k], gi0);
            gf0 = fmaf(hk0, whf[k], gf0);
            gg0 = fmaf(hk0, whg[k], gg0);
            go0 = fmaf(hk0, who[k], go0);
            gi1 = fmaf(hk1, whi[k + 16], gi1);
            gf1 = fmaf(hk1, whf[k + 16], gf1);
            gg1 = fmaf(hk1, whg[k + 16], gg1);
            go1 = fmaf(hk1, who[k + 16], go1);
        }
        float i_ = fast_sig(gi0 + gi1);
        float f_ = fast_sig(gf0 + gf1);
        float o_ = fast_sig(go0 + go1);
        c = fmaf(f_, c, i_ * fast_tanh(gg0 + gg1));
        h = o_ * fast_tanh(c);
        hb[(size_t)t * 32 + lane] = h;
    }
}

// ---------------------------------------------------------------------------
// Phase 3: out[t][512] = tanh(hs@W3+b3)@W4 + b4
// ---------------------------------------------------------------------------
__global__ void __launch_bounds__(256, 1)
phase3_kernel(const float* __restrict__ W3, const float* __restrict__ b3,
              const float* __restrict__ W4, const float* __restrict__ b4,
              float* __restrict__ out)
{
    extern __shared__ float sm[];
    float* hss = sm;               // [128][36]
    float* w3s = hss + TT * 36;    // [32][64]
    float* h3s = w3s + 32 * 64;    // [128][68]
    float* w4s = h3s + TT * 68;    // [64][512]

    const int tid = threadIdx.x;
    const int tx = tid & 7;
    const int ty = tid >> 3;
    const int t0 = blockIdx.x * TT;

    for (int i = tid; i < 32 * 64; i += 256) w3s[i] = W3[i];
    for (int i = tid * 4; i < 64 * 512; i += 1024)
        *(float4*)(w4s + i) = *(const float4*)(W4 + i);
#pragma unroll
    for (int i = 0; i < 4; i++) {
        int slot = tid + i * 256;
        int tok = slot >> 3, kc = slot & 7;
        *(float4*)(hss + tok * 36 + kc * 4) =
            *(const float4*)(g_hs + (size_t)(t0 + tok) * 32 + kc * 4);
    }
    __syncthreads();

    // ---- GEMM4: [128][64], K=32 ----
    float acc2[4][8];
#pragma unroll
    for (int i = 0; i < 4; i++)
#pragma unroll
        for (int j = 0; j < 8; j++) acc2[i][j] = 0.f;

#pragma unroll
    for (int k = 0; k < 32; k++) {
        float4 b0 = *(const float4*)(w3s + k * 64 + tx * 4);
        float4 b1v = *(const float4*)(w3s + k * 64 + tx * 4 + 32);
#pragma unroll
        for (int i = 0; i < 4; i++) {
            float a = hss[(ty * 4 + i) * 36 + k];
            acc2[i][0] = fmaf(a, b0.x, acc2[i][0]);
            acc2[i][1] = fmaf(a, b0.y, acc2[i][1]);
            acc2[i][2] = fmaf(a, b0.z, acc2[i][2]);
            acc2[i][3] = fmaf(a, b0.w, acc2[i][3]);
            acc2[i][4] = fmaf(a, b1v.x, acc2[i][4]);
            acc2[i][5] = fmaf(a, b1v.y, acc2[i][5]);
            acc2[i][6] = fmaf(a, b1v.z, acc2[i][6]);
            acc2[i][7] = fmaf(a, b1v.w, acc2[i][7]);
        }
    }
#pragma unroll
    for (int j2 = 0; j2 < 2; j2++) {
        float4 bb = *(const float4*)(b3 + tx * 4 + 32 * j2);
#pragma unroll
        for (int i = 0; i < 4; i++) {
            float4 hv;
            hv.x = fast_tanh(acc2[i][4 * j2 + 0] + bb.x);
            hv.y = fast_tanh(acc2[i][4 * j2 + 1] + bb.y);
            hv.z = fast_tanh(acc2[i][4 * j2 + 2] + bb.z);
            hv.w = fast_tanh(acc2[i][4 * j2 + 3] + bb.w);
            *(float4*)(h3s + (ty * 4 + i) * 68 + tx * 4 + 32 * j2) = hv;
        }
    }
    __syncthreads();

    // ---- GEMM5: [128][512], K=64, 4 output chunks of 128 ----
    for (int cch = 0; cch < 4; cch++) {
        float acc3[4][16];
#pragma unroll
        for (int i = 0; i < 4; i++)
#pragma unroll
            for (int j = 0; j < 16; j++) acc3[i][j] = 0.f;

#pragma unroll
        for (int k = 0; k < 64; k++) {
            float4 bv[4];
#pragma unroll
            for (int j = 0; j < 4; j++)
                bv[j] = *(const float4*)(w4s + k * 512 + cch * 128 + tx * 4 + 32 * j);
#pragma unroll
            for (int i = 0; i < 4; i++) {
                float a = h3s[(ty * 4 + i) * 68 + k];
#pragma unroll
                for (int j = 0; j < 4; j++) {
                    acc3[i][4 * j + 0] = fmaf(a, bv[j].x, acc3[i][4 * j + 0]);
                    acc3[i][4 * j + 1] = fmaf(a, bv[j].y, acc3[i][4 * j + 1]);
                    acc3[i][4 * j + 2] = fmaf(a, bv[j].z, acc3[i][4 * j + 2]);
                    acc3[i][4 * j + 3] = fmaf(a, bv[j].w, acc3[i][4 * j + 3]);
                }
            }
        }
#pragma unroll
        for (int j = 0; j < 4; j++) {
            float4 bb = *(const float4*)(b4 + cch * 128 + tx * 4 + 32 * j);
#pragma unroll
            for (int i = 0; i < 4; i++) {
                float4 ov;
                ov.x = acc3[i][4 * j + 0] + bb.x;
                ov.y = acc3[i][4 * j + 1] + bb.y;
                ov.z = acc3[i][4 * j + 2] + bb.z;
                ov.w = acc3[i][4 * j + 3] + bb.w;
                *(float4*)(out + (size_t)(t0 + ty * 4 + i) * 512 + cch * 128 + tx * 4 + 32 * j) = ov;
            }
        }
    }
}

// ---------------------------------------------------------------------------
extern "C" void kernel_launch(void* const* d_in, const int* in_sizes, int n_in,
                              void* d_out, int out_size)
{
    (void)in_sizes; (void)n_in; (void)out_size;
    const float* x  = (const float*)d_in[0];
    const float* W1 = (const float*)d_in[1];
    const float* b1 = (const float*)d_in[2];
    const float* W2 = (const float*)d_in[3];
    const float* b2 = (const float*)d_in[4];
    const float* Wx = (const float*)d_in[5];
    const float* Wh = (const float*)d_in[6];
    const float* bl = (const float*)d_in[7];
    const float* W3 = (const float*)d_in[8];
    const float* b3 = (const float*)d_in[9];
    const float* W4 = (const float*)d_in[10];
    const float* b4 = (const float*)d_in[11];
    float* out = (float*)d_out;

    const int P1_SMEM = (TT * 36 + 32 * 32 + TT * 36 + 32 * 64 + TT * 68 + 64 * 128) * 4;
    const int P3_SMEM = (TT * 36 + 32 * 64 + TT * 68 + 64 * 512) * 4;

    cudaFuncSetAttribute(phase1_kernel, cudaFuncAttributeMaxDynamicSharedMemorySize, P1_SMEM);
    cudaFuncSetAttribute(phase3_kernel, cudaFuncAttributeMaxDynamicSharedMemorySize, P3_SMEM);

    phase1_kernel<<<T_TOKENS / TT, 256, P1_SMEM>>>(x, W1, b1, W2, b2, Wx, bl);
    lstm_kernel<<<128, 32>>>(Wh);
    phase3_kernel<<<T_TOKENS / TT, 256, P3_SMEM>>>(W3, b3, W4, b4, out);
}

// round 3
// speedup vs baseline: 1.3362x; 1.3362x over previous
#include <cuda_runtime.h>
#include <math.h>

// ---------------------------------------------------------------------------
// GeneratorRNN: MLP(512->32->64) -> gates(64->128) -> LSTM(H=32) -> MLP(32->64->512)
// B=128, S=1024, F=512, T = 131072 tokens.
// ---------------------------------------------------------------------------

#define T_TOKENS (128 * 1024)
#define TT 128  // tokens per block in GEMM phases

typedef unsigned long long u64;

// Scratch (allocation-free rule: __device__ globals)
__device__ float g_xg[(size_t)T_TOKENS * 128];  // 64 MB: input-side gate preacts
__device__ float g_hs[(size_t)T_TOKENS * 32];   // 16 MB: LSTM hidden outputs

__device__ __forceinline__ float fast_tanh(float x) {
    x = fminf(fmaxf(x, -15.f), 15.f);
    float e = __expf(2.f * x);
    return __fdividef(e - 1.f, e + 1.f);
}
__device__ __forceinline__ float fast_sig(float x) {
    x = fminf(fmaxf(x, -30.f), 30.f);
    return __fdividef(1.f, 1.f + __expf(-x));
}

// f32x2 packed helpers (FFMA2: only reachable via PTX fma.rn.f32x2)
__device__ __forceinline__ u64 pack2(float lo, float hi) {
    u64 r; asm("mov.b64 %0, {%1, %2};" : "=l"(r) : "f"(lo), "f"(hi)); return r;
}
__device__ __forceinline__ u64 fma2(u64 a, u64 b, u64 c) {
    u64 d; asm("fma.rn.f32x2 %0, %1, %2, %3;" : "=l"(d) : "l"(a), "l"(b), "l"(c)); return d;
}
__device__ __forceinline__ float hsum2(u64 v) {
    float lo, hi; asm("mov.b64 {%0, %1}, %2;" : "=f"(lo), "=f"(hi) : "l"(v));
    return lo + hi;
}

// ---------------------------------------------------------------------------
// Phase 1: xg[t][128] = tanh(tanh(x@W1+b1)@W2+b2)@Wx + bl
// Block: 512 threads, 128 tokens (2 per thread-row). h1s aliases xs.
// ---------------------------------------------------------------------------
__global__ void __launch_bounds__(512, 1)
phase1_kernel(const float* __restrict__ x,
              const float* __restrict__ W1, const float* __restrict__ b1,
              const float* __restrict__ W2, const float* __restrict__ b2,
              const float* __restrict__ Wx, const float* __restrict__ bl)
{
    extern __shared__ float sm[];
    float* xs  = sm;               // [128][36]  x k-chunk; later reused as h1s
    float* h1s = sm;               // alias (xs dead before h1s written)
    float* w1s = xs  + TT * 36;    // [32][32]
    float* w2s = w1s + 32 * 32;    // [32][64]
    float* h2s = w2s + 32 * 64;    // [128][68]
    float* wxs = h2s + TT * 68;    // [64][128]

    const int tid = threadIdx.x;
    const int tx = tid & 7;        // output group
    const int ty = tid >> 3;       // token group (x2), 0..63
    const int t0 = blockIdx.x * TT;

    for (int i = tid; i < 32 * 64; i += 512) w2s[i] = W2[i];
    for (int i = tid * 4; i < 64 * 128; i += 2048)
        *(float4*)(wxs + i) = *(const float4*)(Wx + i);

    // ---- GEMM1: [128 tok][32 out], K=512 in chunks of 32 ----
    float acc[2][4];
#pragma unroll
    for (int i = 0; i < 2; i++)
#pragma unroll
        for (int j = 0; j < 4; j++) acc[i][j] = 0.f;

    for (int k0 = 0; k0 < 512; k0 += 32) {
        __syncthreads();
#pragma unroll
        for (int i = 0; i < 2; i++) {
            int slot = tid + i * 512;            // 0..1023
            int tok = slot >> 3, kc = slot & 7;
            float4 v = *(const float4*)(x + (size_t)(t0 + tok) * 512 + k0 + kc * 4);
            *(float4*)(xs + tok * 36 + kc * 4) = v;
        }
        if (tid < 256) {
            int k = tid >> 3, j4 = tid & 7;
            *(float4*)(w1s + k * 32 + j4 * 4) =
                *(const float4*)(W1 + (size_t)(k0 + k) * 32 + j4 * 4);
        }
        __syncthreads();
#pragma unroll
        for (int k = 0; k < 32; k++) {
            float4 bv = *(const float4*)(w1s + k * 32 + tx * 4);
#pragma unroll
            for (int i = 0; i < 2; i++) {
                float a = xs[(ty * 2 + i) * 36 + k];
                acc[i][0] = fmaf(a, bv.x, acc[i][0]);
                acc[i][1] = fmaf(a, bv.y, acc[i][1]);
                acc[i][2] = fmaf(a, bv.z, acc[i][2]);
                acc[i][3] = fmaf(a, bv.w, acc[i][3]);
            }
        }
    }
    __syncthreads();  // all reads of xs complete before h1s (alias) writes
    {
        float4 bb = *(const float4*)(b1 + tx * 4);
#pragma unroll
        for (int i = 0; i < 2; i++) {
            float4 hv;
            hv.x = fast_tanh(acc[i][0] + bb.x);
            hv.y = fast_tanh(acc[i][1] + bb.y);
            hv.z = fast_tanh(acc[i][2] + bb.z);
            hv.w = fast_tanh(acc[i][3] + bb.w);
            *(float4*)(h1s + (ty * 2 + i) * 36 + tx * 4) = hv;
        }
    }
    __syncthreads();

    // ---- GEMM2: [128][64], K=32. outs = {4tx+32j : j=0,1} ----
    float acc2[2][8];
#pragma unroll
    for (int i = 0; i < 2; i++)
#pragma unroll
        for (int j = 0; j < 8; j++) acc2[i][j] = 0.f;

#pragma unroll
    for (int k = 0; k < 32; k++) {
        float4 b0 = *(const float4*)(w2s + k * 64 + tx * 4);
        float4 b1v = *(const float4*)(w2s + k * 64 + tx * 4 + 32);
#pragma unroll
        for (int i = 0; i < 2; i++) {
            float a = h1s[(ty * 2 + i) * 36 + k];
            acc2[i][0] = fmaf(a, b0.x, acc2[i][0]);
            acc2[i][1] = fmaf(a, b0.y, acc2[i][1]);
            acc2[i][2] = fmaf(a, b0.z, acc2[i][2]);
            acc2[i][3] = fmaf(a, b0.w, acc2[i][3]);
            acc2[i][4] = fmaf(a, b1v.x, acc2[i][4]);
            acc2[i][5] = fmaf(a, b1v.y, acc2[i][5]);
            acc2[i][6] = fmaf(a, b1v.z, acc2[i][6]);
            acc2[i][7] = fmaf(a, b1v.w, acc2[i][7]);
        }
    }
#pragma unroll
    for (int j2 = 0; j2 < 2; j2++) {
        float4 bb = *(const float4*)(b2 + tx * 4 + 32 * j2);
#pragma unroll
        for (int i = 0; i < 2; i++) {
            float4 hv;
            hv.x = fast_tanh(acc2[i][4 * j2 + 0] + bb.x);
            hv.y = fast_tanh(acc2[i][4 * j2 + 1] + bb.y);
            hv.z = fast_tanh(acc2[i][4 * j2 + 2] + bb.z);
            hv.w = fast_tanh(acc2[i][4 * j2 + 3] + bb.w);
            *(float4*)(h2s + (ty * 2 + i) * 68 + tx * 4 + 32 * j2) = hv;
        }
    }
    __syncthreads();

    // ---- GEMM3: [128][128], K=64. outs = {4tx+32j : j=0..3} ----
    float acc3[2][16];
#pragma unroll
    for (int i = 0; i < 2; i++)
#pragma unroll
        for (int j = 0; j < 16; j++) acc3[i][j] = 0.f;

#pragma unroll
    for (int k = 0; k < 64; k++) {
        float4 bv[4];
#pragma unroll
        for (int j = 0; j < 4; j++)
            bv[j] = *(const float4*)(wxs + k * 128 + tx * 4 + 32 * j);
#pragma unroll
        for (int i = 0; i < 2; i++) {
            float a = h2s[(ty * 2 + i) * 68 + k];
#pragma unroll
            for (int j = 0; j < 4; j++) {
                acc3[i][4 * j + 0] = fmaf(a, bv[j].x, acc3[i][4 * j + 0]);
                acc3[i][4 * j + 1] = fmaf(a, bv[j].y, acc3[i][4 * j + 1]);
                acc3[i][4 * j + 2] = fmaf(a, bv[j].z, acc3[i][4 * j + 2]);
                acc3[i][4 * j + 3] = fmaf(a, bv[j].w, acc3[i][4 * j + 3]);
            }
        }
    }
#pragma unroll
    for (int j = 0; j < 4; j++) {
        float4 bb = *(const float4*)(bl + tx * 4 + 32 * j);
#pragma unroll
        for (int i = 0; i < 2; i++) {
            float4 ov;
            ov.x = acc3[i][4 * j + 0] + bb.x;
            ov.y = acc3[i][4 * j + 1] + bb.y;
            ov.z = acc3[i][4 * j + 2] + bb.z;
            ov.w = acc3[i][4 * j + 3] + bb.w;
            *(float4*)(g_xg + (size_t)(t0 + ty * 2 + i) * 128 + tx * 4 + 32 * j) = ov;
        }
    }
}

// ---------------------------------------------------------------------------
// Phase 2: LSTM scan. One warp per batch row. Lane n owns gate columns
// {n, n+32, n+64, n+96}. Gate FMAs packed as f32x2 over k-pairs (k, k+16):
// 64 FFMA2 instead of 128 FFMA per step.
// ---------------------------------------------------------------------------
__global__ void __launch_bounds__(32)
lstm_kernel(const float* __restrict__ Wh)
{
    const int b = blockIdx.x;
    const int lane = threadIdx.x;

    u64 wpi[16], wpf[16], wpg[16], wpo[16];
#pragma unroll
    for (int k = 0; k < 16; k++) {
        const float* r0 = Wh + k * 128;
        const float* r1 = Wh + (k + 16) * 128;
        wpi[k] = pack2(r0[lane],      r1[lane]);
        wpf[k] = pack2(r0[32 + lane], r1[32 + lane]);
        wpg[k] = pack2(r0[64 + lane], r1[64 + lane]);
        wpo[k] = pack2(r0[96 + lane], r1[96 + lane]);
    }

    const float* xb = g_xg + (size_t)b * 1024 * 128;
    float* hb = g_hs + (size_t)b * 1024 * 32;

    float c = 0.f, h = 0.f;
    float pi = xb[lane], pf = xb[32 + lane], pg = xb[64 + lane], po = xb[96 + lane];

    for (int t = 0; t < 1024; t++) {
        u64 ai = 0ull, af = 0ull, ag = 0ull, ao = 0ull;  // (0.f, 0.f)
        float xi = pi, xf = pf, xg_ = pg, xo = po;
        if (t < 1023) {  // prefetch next step's gate preacts
            const float* n = xb + (size_t)(t + 1) * 128;
            pi = n[lane]; pf = n[32 + lane]; pg = n[64 + lane]; po = n[96 + lane];
        }
#pragma unroll
        for (int k = 0; k < 16; k++) {
            float hk0 = __shfl_sync(0xffffffffu, h, k);
            float hk1 = __shfl_sync(0xffffffffu, h, k + 16);
            u64 hh = pack2(hk0, hk1);
            ai = fma2(hh, wpi[k], ai);
            af = fma2(hh, wpf[k], af);
            ag = fma2(hh, wpg[k], ag);
            ao = fma2(hh, wpo[k], ao);
        }
        float i_ = fast_sig(xi + hsum2(ai));
        float f_ = fast_sig(xf + hsum2(af));
        float o_ = fast_sig(xo + hsum2(ao));
        float g_ = fast_tanh(xg_ + hsum2(ag));
        c = fmaf(f_, c, i_ * g_);
        h = o_ * fast_tanh(c);
        hb[(size_t)t * 32 + lane] = h;
    }
}

// ---------------------------------------------------------------------------
// Phase 3: out[t][512] = tanh(hs@W3+b3)@W4 + b4. 512 threads, 128 tokens.
// ---------------------------------------------------------------------------
__global__ void __launch_bounds__(512, 1)
phase3_kernel(const float* __restrict__ W3, const float* __restrict__ b3,
              const float* __restrict__ W4, const float* __restrict__ b4,
              float* __restrict__ out)
{
    extern __shared__ float sm[];
    float* hss = sm;               // [128][36]
    float* w3s = hss + TT * 36;    // [32][64]
    float* h3s = w3s + 32 * 64;    // [128][68]
    float* w4s = h3s + TT * 68;    // [64][512]

    const int tid = threadIdx.x;
    const int tx = tid & 7;
    const int ty = tid >> 3;       // 0..63
    const int t0 = blockIdx.x * TT;

    for (int i = tid; i < 32 * 64; i += 512) w3s[i] = W3[i];
    for (int i = tid * 4; i < 64 * 512; i += 2048)
        *(float4*)(w4s + i) = *(const float4*)(W4 + i);
#pragma unroll
    for (int i = 0; i < 2; i++) {
        int slot = tid + i * 512;
        int tok = slot >> 3, kc = slot & 7;
        *(float4*)(hss + tok * 36 + kc * 4) =
            *(const float4*)(g_hs + (size_t)(t0 + tok) * 32 + kc * 4);
    }
    __syncthreads();

    // ---- GEMM4: [128][64], K=32 ----
    float acc2[2][8];
#pragma unroll
    for (int i = 0; i < 2; i++)
#pragma unroll
        for (int j = 0; j < 8; j++) acc2[i][j] = 0.f;

#pragma unroll
    for (int k = 0; k < 32; k++) {
        float4 b0 = *(const float4*)(w3s + k * 64 + tx * 4);
        float4 b1v = *(const float4*)(w3s + k * 64 + tx * 4 + 32);
#pragma unroll
        for (int i = 0; i < 2; i++) {
            float a = hss[(ty * 2 + i) * 36 + k];
            acc2[i][0] = fmaf(a, b0.x, acc2[i][0]);
            acc2[i][1] = fmaf(a, b0.y, acc2[i][1]);
            acc2[i][2] = fmaf(a, b0.z, acc2[i][2]);
            acc2[i][3] = fmaf(a, b0.w, acc2[i][3]);
            acc2[i][4] = fmaf(a, b1v.x, acc2[i][4]);
            acc2[i][5] = fmaf(a, b1v.y, acc2[i][5]);
            acc2[i][6] = fmaf(a, b1v.z, acc2[i][6]);
            acc2[i][7] = fmaf(a, b1v.w, acc2[i][7]);
        }
    }
#pragma unroll
    for (int j2 = 0; j2 < 2; j2++) {
        float4 bb = *(const float4*)(b3 + tx * 4 + 32 * j2);
#pragma unroll
        for (int i = 0; i < 2; i++) {
            float4 hv;
            hv.x = fast_tanh(acc2[i][4 * j2 + 0] + bb.x);
            hv.y = fast_tanh(acc2[i][4 * j2 + 1] + bb.y);
            hv.z = fast_tanh(acc2[i][4 * j2 + 2] + bb.z);
            hv.w = fast_tanh(acc2[i][4 * j2 + 3] + bb.w);
            *(float4*)(h3s + (ty * 2 + i) * 68 + tx * 4 + 32 * j2) = hv;
        }
    }
    __syncthreads();

    // ---- GEMM5: [128][512], K=64, 4 output chunks of 128 ----
    for (int cch = 0; cch < 4; cch++) {
        float acc3[2][16];
#pragma unroll
        for (int i = 0; i < 2; i++)
#pragma unroll
            for (int j = 0; j < 16; j++) acc3[i][j] = 0.f;

#pragma unroll
        for (int k = 0; k < 64; k++) {
            float4 bv[4];
#pragma unroll
            for (int j = 0; j < 4; j++)
                bv[j] = *(const float4*)(w4s + k * 512 + cch * 128 + tx * 4 + 32 * j);
#pragma unroll
            for (int i = 0; i < 2; i++) {
                float a = h3s[(ty * 2 + i) * 68 + k];
#pragma unroll
                for (int j = 0; j < 4; j++) {
                    acc3[i][4 * j + 0] = fmaf(a, bv[j].x, acc3[i][4 * j + 0]);
                    acc3[i][4 * j + 1] = fmaf(a, bv[j].y, acc3[i][4 * j + 1]);
                    acc3[i][4 * j + 2] = fmaf(a, bv[j].z, acc3[i][4 * j + 2]);
                    acc3[i][4 * j + 3] = fmaf(a, bv[j].w, acc3[i][4 * j + 3]);
                }
            }
        }
#pragma unroll
        for (int j = 0; j < 4; j++) {
            float4 bb = *(const float4*)(b4 + cch * 128 + tx * 4 + 32 * j);
#pragma unroll
            for (int i = 0; i < 2; i++) {
                float4 ov;
                ov.x = acc3[i][4 * j + 0] + bb.x;
                ov.y = acc3[i][4 * j + 1] + bb.y;
                ov.z = acc3[i][4 * j + 2] + bb.z;
                ov.w = acc3[i][4 * j + 3] + bb.w;
                *(float4*)(out + (size_t)(t0 + ty * 2 + i) * 512 + cch * 128 + tx * 4 + 32 * j) = ov;
            }
        }
    }
}

// ---------------------------------------------------------------------------
extern "C" void kernel_launch(void* const* d_in, const int* in_sizes, int n_in,
                              void* d_out, int out_size)
{
    (void)in_sizes; (void)n_in; (void)out_size;
    const float* x  = (const float*)d_in[0];
    const float* W1 = (const float*)d_in[1];
    const float* b1 = (const float*)d_in[2];
    const float* W2 = (const float*)d_in[3];
    const float* b2 = (const float*)d_in[4];
    const float* Wx = (const float*)d_in[5];
    const float* Wh = (const float*)d_in[6];
    const float* bl = (const float*)d_in[7];
    const float* W3 = (const float*)d_in[8];
    const float* b3 = (const float*)d_in[9];
    const float* W4 = (const float*)d_in[10];
    const float* b4 = (const float*)d_in[11];
    float* out = (float*)d_out;

    const int P1_SMEM = (TT * 36 + 32 * 32 + 32 * 64 + TT * 68 + 64 * 128) * 4;
    const int P3_SMEM = (TT * 36 + 32 * 64 + TT * 68 + 64 * 512) * 4;

    cudaFuncSetAttribute(phase1_kernel, cudaFuncAttributeMaxDynamicSharedMemorySize, P1_SMEM);
    cudaFuncSetAttribute(phase3_kernel, cudaFuncAttributeMaxDynamicSharedMemorySize, P3_SMEM);

    phase1_kernel<<<T_TOKENS / TT, 512, P1_SMEM>>>(x, W1, b1, W2, b2, Wx, bl);
    lstm_kernel<<<128, 32>>>(Wh);
    phase3_kernel<<<T_TOKENS / TT, 512, P3_SMEM>>>(W3, b3, W4, b4, out);
}